// round 13
// baseline (speedup 1.0000x reference)
#include <cuda_runtime.h>
#include <cstdint>

#define T_LEN   1048576
#define KSTEPS  512
#define NSLOTS  4
#define NCHUNK  (T_LEN / KSTEPS)

// shared memory layout (bytes)
#define OFF_PF   0                         // p_full[4]   (8B each)
#define OFF_PC   32                        // p_cons[4]
#define OFF_WF   64                        // w_full[4]
#define OFF_WE   96                        // w_free[4]
#define OFF_P    256                       // p ring: 4 slots x 512 steps x 64B
#define PSLOT    (KSTEPS * 64)
#define OFF_W    (OFF_P + NSLOTS * PSLOT)  // w ring: 4 slots x 512 steps x 32B
#define WSLOT    (KSTEPS * 32)
#define SMEM_SZ  (OFF_W + NSLOTS * WSLOT + 256)  // pad for prefetch overrun

typedef unsigned long long ull;
typedef unsigned int u32;

__device__ __forceinline__ void mbar_init(u32 a, u32 cnt) {
    asm volatile("mbarrier.init.shared.b64 [%0], %1;" :: "r"(a), "r"(cnt) : "memory");
}
__device__ __forceinline__ void mbar_arrive(u32 a) {
    asm volatile("mbarrier.arrive.release.cta.shared::cta.b64 _, [%0];" :: "r"(a) : "memory");
}
__device__ __forceinline__ void mbar_wait(u32 a, u32 par) {
    u32 done;
    asm volatile(
        "{\n\t.reg .pred p;\n\t"
        "mbarrier.try_wait.parity.acquire.cta.shared::cta.b64 p, [%1], %2;\n\t"
        "selp.b32 %0, 1, 0, p;\n\t}"
        : "=r"(done) : "r"(a), "r"(par) : "memory");
    if (!done) {
        asm volatile(
            "{\n\t.reg .pred P1;\n\t"
            "WL_%=:\n\t"
            "mbarrier.try_wait.parity.acquire.cta.shared::cta.b64 P1, [%0], %1, 0x989680;\n\t"
            "@P1 bra.uni WD_%=;\n\t"
            "bra.uni WL_%=;\n\t"
            "WD_%=:\n\t}"
            :: "r"(a), "r"(par) : "memory");
    }
}

// packed add: two bit-exact IEEE-rn f32 adds in one instruction.
__device__ __forceinline__ ull add2(ull a, ull c) {
    ull r; asm("add.rn.f32x2 %0, %1, %2;" : "=l"(r) : "l"(a), "l"(c));
    return r;
}
// pack/unpack in C++: resolved by register allocation, not real MOVs.
__device__ __forceinline__ ull fpack2(float lo, float hi) {
    union { float f[2]; ull u; } v; v.f[0] = lo; v.f[1] = hi; return v.u;
}
__device__ __forceinline__ float flo(ull x) {
    union { ull u; float f[2]; } v; v.u = x; return v.f[0];
}
__device__ __forceinline__ float fhi(ull x) {
    union { ull u; float f[2]; } v; v.u = x; return v.f[1];
}

__global__ void __launch_bounds__(448, 1)
va_main(const float* __restrict__ y, const float* __restrict__ sp, float* __restrict__ out)
{
    extern __shared__ char smem[];
    u32 sb = (u32)__cvta_generic_to_shared(smem);
    int tid = threadIdx.x, wid = tid >> 5, lane = tid & 31;

    if (tid == 0) {
        for (int s = 0; s < NSLOTS; s++) {
            mbar_init(sb + OFF_PF + 8 * s, 64); // 64 fetch lanes arrive
            mbar_init(sb + OFF_PC + 8 * s, 1);  // producer arrives
            mbar_init(sb + OFF_WF + 8 * s, 1);  // producer arrives
            mbar_init(sb + OFF_WE + 8 * s, 4);  // 4 bit-warp leaders arrive
        }
    }
    __syncthreads();

    // wid%4 = SMSP. Producer = wid 11, alone on SMSP3 (3, 7 exit).
    // Active: 0,1 = helpers; 2,4,5,6 = bit warps; 11 = producer.
    // 3,7,8,9,10,12,13 exit (fewer live warps -> less crossbar/L1TEX noise).
    if (wid == 3 || wid == 7 || (wid >= 8 && wid != 11)) return;

    if (wid == 11) {
        // -------- serial Viterbi producer, private SMSP --------
        // Split-pair layout: E0=(w0,w2) O0=(w1,w3) E1=(w4,w6) O1=(w5,w7).
        // 8 packed ADD2 do all 16 adds; 8 scalar FMNMX read pair components.
        // Distance-3 prefetch: loads issue ~3 steps ahead of consumption.
        if (lane == 0) {
            ull E0 = 0ull, O0 = 0ull, E1 = 0ull, O1 = 0ull;
            for (int c = 0; c < NCHUNK; c++) {
                int s = c & 3;
                mbar_wait(sb + OFF_PF + 8 * s, (c >> 2) & 1);
                if (c >= NSLOTS) mbar_wait(sb + OFF_WE + 8 * s, ((c - NSLOTS) >> 2) & 1);
                const ulonglong2* __restrict__ pp =
                    (const ulonglong2*)(smem + OFF_P + s * PSLOT);   // 4 per step
                float4* __restrict__ wp =
                    (float4*)(smem + OFF_W + s * WSLOT);             // 2 per step
                // distance-3 prefetch (ring pad covers the tail overrun;
                // overrun values are rotated but never consumed)
                ulonglong2 a0 = pp[0],  a1 = pp[1],  a2 = pp[2],  a3 = pp[3];
                ulonglong2 b0 = pp[4],  b1 = pp[5],  b2 = pp[6],  b3 = pp[7];
                ulonglong2 d0 = pp[8],  d1 = pp[9],  d2 = pp[10], d3 = pp[11];
                #pragma unroll 8
                for (int k = 0; k < KSTEPS; k++) {
                    ulonglong2 n0 = pp[4 * k + 12];
                    // a_.x = even pair (p_e0,p_e1), a_.y = odd pair (helper layout)
                    ull mEa = add2(E0, a0.x);   // (m0,  m2)
                    ull mOa = add2(O0, a0.y);   // (m1,  m3)
                    ulonglong2 n1 = pp[4 * k + 13];
                    ull mEb = add2(E1, a1.x);   // (m4,  m6)
                    ull mOb = add2(O1, a1.y);   // (m5,  m7)
                    ulonglong2 n2 = pp[4 * k + 14];
                    ull mEc = add2(E0, a2.x);   // (m8,  m10)
                    ull mOc = add2(O0, a2.y);   // (m9,  m11)
                    ulonglong2 n3 = pp[4 * k + 15];
                    ull mEd = add2(E1, a3.x);   // (m12, m14)
                    ull mOd = add2(O1, a3.y);   // (m13, m15)
                    // o[q] = min(m[2q], m[2q+1]) -- scalar mins on components
                    float o0 = fminf(flo(mEa), flo(mOa));
                    float o1 = fminf(fhi(mEa), fhi(mOa));
                    float o2 = fminf(flo(mEb), flo(mOb));
                    float o3 = fminf(fhi(mEb), fhi(mOb));
                    float o4 = fminf(flo(mEc), flo(mOc));
                    float o5 = fminf(fhi(mEc), fhi(mOc));
                    float o6 = fminf(flo(mEd), flo(mOd));
                    float o7 = fminf(fhi(mEd), fhi(mOd));
                    // export in split order (bit warps un-permute for free)
                    wp[2 * k + 0] = make_float4(o0, o2, o1, o3);
                    wp[2 * k + 1] = make_float4(o4, o6, o5, o7);
                    E0 = fpack2(o0, o2); O0 = fpack2(o1, o3);
                    E1 = fpack2(o4, o6); O1 = fpack2(o5, o7);
                    a0 = b0; a1 = b1; a2 = b2; a3 = b3;
                    b0 = d0; b1 = d1; b2 = d2; b3 = d3;
                    d0 = n0; d1 = n1; d2 = n2; d3 = n3;
                }
                mbar_arrive(sb + OFF_PC + 8 * s);
                mbar_arrive(sb + OFF_WF + 8 * s);
            }
        }
    } else if (wid < 2) {
        // -------- branch-metric producers: p[t][u] = |y[t] - sp[u]|,
        // written in split-pair order (4q, 4q+2, 4q+1, 4q+3) --------
        int base = wid * 32 + lane;         // 0..63
        int quad = base & 3;                // fixed 4-state group per lane
        float s0 = sp[quad * 4 + 0], s1 = sp[quad * 4 + 2];
        float s2 = sp[quad * 4 + 1], s3 = sp[quad * 4 + 3];
        for (int c = 0; c < NCHUNK; c++) {
            int s = c & 3;
            if (c >= NSLOTS) mbar_wait(sb + OFF_PC + 8 * s, ((c - NSLOTS) >> 2) & 1);
            float4* __restrict__ pb = (float4*)(smem + OFF_P + s * PSLOT);
            const float* yc = y + c * KSTEPS;
            #pragma unroll 4
            for (int it = 0; it < 32; it++) {
                int idx = it * 64 + base;
                int k = idx >> 2;           // step within chunk
                float yv = __ldg(&yc[k]);
                pb[k * 4 + quad] = make_float4(fabsf(yv - s0), fabsf(yv - s1),
                                               fabsf(yv - s2), fabsf(yv - s3));
            }
            mbar_arrive(sb + OFF_PF + 8 * s);
        }
    } else {
        // -------- bit extractors: bit[t] = argmin(w_t) % 2. --------
        // wids {2,4,5,6} -> bit-warp index 0..3; each thread does 4 steps/chunk.
        int b4 = (wid == 2) ? 0 : (wid - 3);
        int btid = b4 * 32 + lane;          // 0..127
        if (btid == 0) out[0] = 0.0f;       // v_0 = zeros -> argmin = 0 -> bit 0
        const float4* wr = (const float4*)(smem + OFF_W);
        for (int c = 0; c < NCHUNK; c++) {
            int s = c & 3;
            mbar_wait(sb + OFF_WF + 8 * s, (c >> 2) & 1);
            #pragma unroll
            for (int r = 0; r < 4; r++) {
                int k = r * 128 + btid;
                int i = c * KSTEPS + k;     // producer step index; W[i] = w_{i+1}
                if (i != T_LEN - 1) {
                    const float4* p = wr + (size_t)(s * KSTEPS + k) * 2;
                    float4 a = p[0], b = p[1];
                    // W stored split-pair: (o0,o2,o1,o3 | o4,o6,o5,o7); scan in
                    // LOGICAL order o0..o7 (strict < = first-index ties, matching
                    // jnp.argmin over the duplicated 16-vector).
                    float best = a.x; int bi = 0;            // o0
                    if (a.z < best) { best = a.z; bi = 1; }  // o1
                    if (a.y < best) { best = a.y; bi = 2; }  // o2
                    if (a.w < best) { best = a.w; bi = 3; }  // o3
                    if (b.x < best) { best = b.x; bi = 4; }  // o4
                    if (b.z < best) { best = b.z; bi = 5; }  // o5
                    if (b.y < best) { best = b.y; bi = 6; }  // o6
                    if (b.w < best) {            bi = 7; }   // o7
                    out[i + 1] = (float)(bi & 1);
                }
            }
            __syncwarp();
            if (lane == 0) mbar_arrive(sb + OFF_WE + 8 * s);
        }
    }
}

extern "C" void kernel_launch(void* const* d_in, const int* in_sizes, int n_in,
                              void* d_out, int out_size)
{
    const float* a = (const float*)d_in[0];
    const float* b = (const float*)d_in[1];
    const float* y;
    const float* sp;
    if (in_sizes[0] == 16) { sp = a; y = b; }
    else                   { y = a;  sp = b; }

    cudaFuncSetAttribute(va_main, cudaFuncAttributeMaxDynamicSharedMemorySize, SMEM_SZ);
    va_main<<<1, 448, SMEM_SZ>>>(y, sp, (float*)d_out);
}

// round 14
// speedup vs baseline: 1.1613x; 1.1613x over previous
#include <cuda_runtime.h>
#include <cstdint>

#define T_LEN   1048576
#define KSTEPS  1024
#define NSLOTS  2
#define NCHUNK  (T_LEN / KSTEPS)

// shared memory layout (bytes)
#define OFF_PF   0                         // p_full[2]   (8B each)
#define OFF_PC   32                        // p_cons[2]
#define OFF_WF   64                        // w_full[2]
#define OFF_WE   96                        // w_free[2]
#define OFF_P    256                       // p ring: 2 slots x 1024 steps x 64B
#define PSLOT    (KSTEPS * 64)
#define OFF_W    (OFF_P + NSLOTS * PSLOT)  // w ring: 2 slots x 1024 steps x 32B
#define WSLOT    (KSTEPS * 32)
#define SMEM_SZ  (OFF_W + NSLOTS * WSLOT + 256)  // pad for prefetch overrun

typedef unsigned long long ull;
typedef unsigned int u32;

__device__ __forceinline__ void mbar_init(u32 a, u32 cnt) {
    asm volatile("mbarrier.init.shared.b64 [%0], %1;" :: "r"(a), "r"(cnt) : "memory");
}
__device__ __forceinline__ void mbar_arrive(u32 a) {
    asm volatile("mbarrier.arrive.release.cta.shared::cta.b64 _, [%0];" :: "r"(a) : "memory");
}
__device__ __forceinline__ void mbar_wait(u32 a, u32 par) {
    u32 done;
    asm volatile(
        "{\n\t.reg .pred p;\n\t"
        "mbarrier.try_wait.parity.acquire.cta.shared::cta.b64 p, [%1], %2;\n\t"
        "selp.b32 %0, 1, 0, p;\n\t}"
        : "=r"(done) : "r"(a), "r"(par) : "memory");
    if (!done) {
        asm volatile(
            "{\n\t.reg .pred P1;\n\t"
            "WL_%=:\n\t"
            "mbarrier.try_wait.parity.acquire.cta.shared::cta.b64 P1, [%0], %1, 0x989680;\n\t"
            "@P1 bra.uni WD_%=;\n\t"
            "bra.uni WL_%=;\n\t"
            "WD_%=:\n\t}"
            :: "r"(a), "r"(par) : "memory");
    }
}

// packed add: two bit-exact IEEE-rn f32 adds in one instruction.
__device__ __forceinline__ ull add2(ull a, ull c) {
    ull r; asm("add.rn.f32x2 %0, %1, %2;" : "=l"(r) : "l"(a), "l"(c));
    return r;
}
// pack/unpack in C++: resolved by register allocation, not real MOVs.
__device__ __forceinline__ ull fpack2(float lo, float hi) {
    union { float f[2]; ull u; } v; v.f[0] = lo; v.f[1] = hi; return v.u;
}
__device__ __forceinline__ float flo(ull x) {
    union { ull u; float f[2]; } v; v.u = x; return v.f[0];
}
__device__ __forceinline__ float fhi(ull x) {
    union { ull u; float f[2]; } v; v.u = x; return v.f[1];
}

__global__ void __launch_bounds__(448, 1)
va_main(const float* __restrict__ y, const float* __restrict__ sp, float* __restrict__ out)
{
    extern __shared__ char smem[];
    u32 sb = (u32)__cvta_generic_to_shared(smem);
    int tid = threadIdx.x, wid = tid >> 5, lane = tid & 31;

    if (tid == 0) {
        for (int s = 0; s < NSLOTS; s++) {
            mbar_init(sb + OFF_PF + 8 * s, 64); // 64 fetch lanes arrive
            mbar_init(sb + OFF_PC + 8 * s, 1);  // producer arrives
            mbar_init(sb + OFF_WF + 8 * s, 1);  // producer arrives
            mbar_init(sb + OFF_WE + 8 * s, 8);  // 8 bit-warp leaders arrive
        }
    }
    __syncthreads();

    // Warp->SMSP map is wid%4. Producer owns SMSP3 EXCLUSIVELY: it is wid 11,
    // and the other SMSP3 warps (3, 7) plus spare warp 13 exit immediately.
    if (wid == 3 || wid == 7 || wid == 13) return;

    if (wid == 11) {
        // -------- serial Viterbi producer, private SMSP --------
        // Split-pair layout: E0=(w0,w2) O0=(w1,w3) E1=(w4,w6) O1=(w5,w7).
        // 8 packed ADD2 do all 16 adds; 8 scalar FMNMX read pair components.
        // Distance-2 prefetch. KSTEPS=1024/NSLOTS=2: half the chunk-boundary
        // mbarrier crossings vs 512/4 at identical pipeline depth in steps.
        if (lane == 0) {
            ull E0 = 0ull, O0 = 0ull, E1 = 0ull, O1 = 0ull;
            for (int c = 0; c < NCHUNK; c++) {
                int s = c & 1;
                mbar_wait(sb + OFF_PF + 8 * s, (c >> 1) & 1);
                if (c >= NSLOTS) mbar_wait(sb + OFF_WE + 8 * s, ((c - NSLOTS) >> 1) & 1);
                const ulonglong2* __restrict__ pp =
                    (const ulonglong2*)(smem + OFF_P + s * PSLOT);   // 4 per step
                float4* __restrict__ wp =
                    (float4*)(smem + OFF_W + s * WSLOT);             // 2 per step
                // distance-2 prefetch (tail overrun reads pad/adjacent ring,
                // values rotated but never consumed)
                ulonglong2 a0 = pp[0], a1 = pp[1], a2 = pp[2], a3 = pp[3];
                ulonglong2 b0 = pp[4], b1 = pp[5], b2 = pp[6], b3 = pp[7];
                #pragma unroll 16
                for (int k = 0; k < KSTEPS; k++) {
                    ulonglong2 c0 = pp[4 * k +  8];
                    // a_.x = even pair (p_e0,p_e1), a_.y = odd pair (helper layout)
                    ull mEa = add2(E0, a0.x);   // (m0,  m2)
                    ull mOa = add2(O0, a0.y);   // (m1,  m3)
                    ulonglong2 c1 = pp[4 * k +  9];
                    ull mEb = add2(E1, a1.x);   // (m4,  m6)
                    ull mOb = add2(O1, a1.y);   // (m5,  m7)
                    ulonglong2 c2 = pp[4 * k + 10];
                    ull mEc = add2(E0, a2.x);   // (m8,  m10)
                    ull mOc = add2(O0, a2.y);   // (m9,  m11)
                    ulonglong2 c3 = pp[4 * k + 11];
                    ull mEd = add2(E1, a3.x);   // (m12, m14)
                    ull mOd = add2(O1, a3.y);   // (m13, m15)
                    // o[q] = min(m[2q], m[2q+1]) -- scalar mins on components
                    float o0 = fminf(flo(mEa), flo(mOa));
                    float o1 = fminf(fhi(mEa), fhi(mOa));
                    float o2 = fminf(flo(mEb), flo(mOb));
                    float o3 = fminf(fhi(mEb), fhi(mOb));
                    float o4 = fminf(flo(mEc), flo(mOc));
                    float o5 = fminf(fhi(mEc), fhi(mOc));
                    float o6 = fminf(flo(mEd), flo(mOd));
                    float o7 = fminf(fhi(mEd), fhi(mOd));
                    // export in split order (bit warps un-permute for free)
                    wp[2 * k + 0] = make_float4(o0, o2, o1, o3);
                    wp[2 * k + 1] = make_float4(o4, o6, o5, o7);
                    E0 = fpack2(o0, o2); O0 = fpack2(o1, o3);
                    E1 = fpack2(o4, o6); O1 = fpack2(o5, o7);
                    a0 = b0; a1 = b1; a2 = b2; a3 = b3;
                    b0 = c0; b1 = c1; b2 = c2; b3 = c3;
                }
                mbar_arrive(sb + OFF_PC + 8 * s);
                mbar_arrive(sb + OFF_WF + 8 * s);
            }
        }
    } else if (wid < 2) {
        // -------- branch-metric producers: p[t][u] = |y[t] - sp[u]|,
        // written in split-pair order (4q, 4q+2, 4q+1, 4q+3) --------
        int base = wid * 32 + lane;         // 0..63
        int quad = base & 3;                // fixed 4-state group per lane
        float s0 = sp[quad * 4 + 0], s1 = sp[quad * 4 + 2];
        float s2 = sp[quad * 4 + 1], s3 = sp[quad * 4 + 3];
        for (int c = 0; c < NCHUNK; c++) {
            int s = c & 1;
            if (c >= NSLOTS) mbar_wait(sb + OFF_PC + 8 * s, ((c - NSLOTS) >> 1) & 1);
            float4* __restrict__ pb = (float4*)(smem + OFF_P + s * PSLOT);
            const float* yc = y + c * KSTEPS;
            #pragma unroll 4
            for (int it = 0; it < 64; it++) {
                int idx = it * 64 + base;
                int k = idx >> 2;           // step within chunk
                float yv = __ldg(&yc[k]);
                pb[k * 4 + quad] = make_float4(fabsf(yv - s0), fabsf(yv - s1),
                                               fabsf(yv - s2), fabsf(yv - s3));
            }
            mbar_arrive(sb + OFF_PF + 8 * s);
        }
    } else {
        // -------- bit extractors: bit[t] = argmin(w_t) % 2. --------
        // wids {2,4,5,6,8,9,10,12} -> bit-warp index 0..7 (none on SMSP3).
        int b8 = (wid < 3) ? (wid - 2) : (wid < 7) ? (wid - 3)
                 : (wid < 11) ? (wid - 4) : (wid - 5);
        int btid = b8 * 32 + lane;          // 0..255
        if (btid == 0) out[0] = 0.0f;       // v_0 = zeros -> argmin = 0 -> bit 0
        const float4* wr = (const float4*)(smem + OFF_W);
        for (int c = 0; c < NCHUNK; c++) {
            int s = c & 1;
            mbar_wait(sb + OFF_WF + 8 * s, (c >> 1) & 1);
            #pragma unroll
            for (int r = 0; r < 4; r++) {
                int k = r * 256 + btid;
                int i = c * KSTEPS + k;     // producer step index; W[i] = w_{i+1}
                if (i != T_LEN - 1) {
                    const float4* p = wr + (size_t)(s * KSTEPS + k) * 2;
                    float4 a = p[0], b = p[1];
                    // W stored split-pair: (o0,o2,o1,o3 | o4,o6,o5,o7); scan in
                    // LOGICAL order o0..o7 (strict < = first-index ties, matching
                    // jnp.argmin over the duplicated 16-vector).
                    float best = a.x; int bi = 0;            // o0
                    if (a.z < best) { best = a.z; bi = 1; }  // o1
                    if (a.y < best) { best = a.y; bi = 2; }  // o2
                    if (a.w < best) { best = a.w; bi = 3; }  // o3
                    if (b.x < best) { best = b.x; bi = 4; }  // o4
                    if (b.z < best) { best = b.z; bi = 5; }  // o5
                    if (b.y < best) { best = b.y; bi = 6; }  // o6
                    if (b.w < best) {            bi = 7; }   // o7
                    out[i + 1] = (float)(bi & 1);
                }
            }
            __syncwarp();
            if (lane == 0) mbar_arrive(sb + OFF_WE + 8 * s);
        }
    }
}

extern "C" void kernel_launch(void* const* d_in, const int* in_sizes, int n_in,
                              void* d_out, int out_size)
{
    const float* a = (const float*)d_in[0];
    const float* b = (const float*)d_in[1];
    const float* y;
    const float* sp;
    if (in_sizes[0] == 16) { sp = a; y = b; }
    else                   { y = a;  sp = b; }

    cudaFuncSetAttribute(va_main, cudaFuncAttributeMaxDynamicSharedMemorySize, SMEM_SZ);
    va_main<<<1, 448, SMEM_SZ>>>(y, sp, (float*)d_out);
}

// round 15
// speedup vs baseline: 1.2540x; 1.0799x over previous
#include <cuda_runtime.h>
#include <cstdint>

#define T_LEN   1048576
#define KSTEPS  1024
#define NSLOTS  2
#define NCHUNK  (T_LEN / KSTEPS)

// shared memory layout (bytes)
#define OFF_PF   0                         // p_full[2]   (8B each)
#define OFF_PC   32                        // p_cons[2]
#define OFF_WF   64                        // w_full[2]
#define OFF_WE   96                        // w_free[2]
#define OFF_P    256                       // p ring: 2 slots x 1024 steps x 64B
#define PSLOT    (KSTEPS * 64)
#define OFF_W    (OFF_P + NSLOTS * PSLOT)  // w ring: 2 slots x 256 ckpts x 32B
#define WSLOT    (KSTEPS / 4 * 32)
#define SMEM_SZ  (OFF_W + NSLOTS * WSLOT + 256)  // pad for prefetch overrun

typedef unsigned long long ull;
typedef unsigned int u32;

__device__ __forceinline__ void mbar_init(u32 a, u32 cnt) {
    asm volatile("mbarrier.init.shared.b64 [%0], %1;" :: "r"(a), "r"(cnt) : "memory");
}
__device__ __forceinline__ void mbar_arrive(u32 a) {
    asm volatile("mbarrier.arrive.release.cta.shared::cta.b64 _, [%0];" :: "r"(a) : "memory");
}
__device__ __forceinline__ void mbar_wait(u32 a, u32 par) {
    u32 done;
    asm volatile(
        "{\n\t.reg .pred p;\n\t"
        "mbarrier.try_wait.parity.acquire.cta.shared::cta.b64 p, [%1], %2;\n\t"
        "selp.b32 %0, 1, 0, p;\n\t}"
        : "=r"(done) : "r"(a), "r"(par) : "memory");
    if (!done) {
        asm volatile(
            "{\n\t.reg .pred P1;\n\t"
            "WL_%=:\n\t"
            "mbarrier.try_wait.parity.acquire.cta.shared::cta.b64 P1, [%0], %1, 0x989680;\n\t"
            "@P1 bra.uni WD_%=;\n\t"
            "bra.uni WL_%=;\n\t"
            "WD_%=:\n\t}"
            :: "r"(a), "r"(par) : "memory");
    }
}

// packed add: two bit-exact IEEE-rn f32 adds in one instruction.
__device__ __forceinline__ ull add2(ull a, ull c) {
    ull r; asm("add.rn.f32x2 %0, %1, %2;" : "=l"(r) : "l"(a), "l"(c));
    return r;
}
// pack/unpack in C++: resolved by register allocation, not real MOVs.
__device__ __forceinline__ ull fpack2(float lo, float hi) {
    union { float f[2]; ull u; } v; v.f[0] = lo; v.f[1] = hi; return v.u;
}
__device__ __forceinline__ float flo(ull x) {
    union { ull u; float f[2]; } v; v.u = x; return v.f[0];
}
__device__ __forceinline__ float fhi(ull x) {
    union { ull u; float f[2]; } v; v.u = x; return v.f[1];
}

// first-index argmin over logical w0..w7, return (idx & 1) as float.
// strict < keeps lowest index = jnp.argmin tie-break on the duplicated 16-vec.
__device__ __forceinline__ float bit_of(float w0, float w1, float w2, float w3,
                                        float w4, float w5, float w6, float w7) {
    float best = w0; int bi = 0;
    if (w1 < best) { best = w1; bi = 1; }
    if (w2 < best) { best = w2; bi = 2; }
    if (w3 < best) { best = w3; bi = 3; }
    if (w4 < best) { best = w4; bi = 4; }
    if (w5 < best) { best = w5; bi = 5; }
    if (w6 < best) { best = w6; bi = 6; }
    if (w7 < best) {            bi = 7; }
    return (float)(bi & 1);
}

__global__ void __launch_bounds__(448, 1)
va_main(const float* __restrict__ y, const float* __restrict__ sp, float* __restrict__ out)
{
    extern __shared__ char smem[];
    u32 sb = (u32)__cvta_generic_to_shared(smem);
    int tid = threadIdx.x, wid = tid >> 5, lane = tid & 31;

    if (tid == 0) {
        for (int s = 0; s < NSLOTS; s++) {
            mbar_init(sb + OFF_PF + 8 * s, 64); // 64 fetch lanes arrive
            mbar_init(sb + OFF_PC + 8 * s, 9);  // producer + 8 bit leaders
            mbar_init(sb + OFF_WF + 8 * s, 1);  // producer arrives
            mbar_init(sb + OFF_WE + 8 * s, 8);  // 8 bit-warp leaders arrive
        }
    }
    __syncthreads();

    // wid%4 = SMSP. Producer = wid 11, alone on SMSP3 (3, 7, 13 exit).
    if (wid == 3 || wid == 7 || wid == 13) return;

    if (wid == 11) {
        // -------- serial Viterbi producer, private SMSP --------
        // Split-pair layout: E0=(w0,w2) O0=(w1,w3) E1=(w4,w6) O1=(w5,w7).
        // 8 packed ADD2 + 8 scalar FMNMX per step; distance-2 prefetch.
        // Exports only CHECKPOINTS (pre-step w at k%4==0): bit warps replay
        // the <=3 intermediate ACS steps themselves (monotone min => the
        // replay is bit-exact). Producer store traffic drops 4x.
        if (lane == 0) {
            ull E0 = 0ull, O0 = 0ull, E1 = 0ull, O1 = 0ull;
            for (int c = 0; c < NCHUNK; c++) {
                int s = c & 1;
                mbar_wait(sb + OFF_PF + 8 * s, (c >> 1) & 1);
                if (c >= NSLOTS) mbar_wait(sb + OFF_WE + 8 * s, ((c - NSLOTS) >> 1) & 1);
                const ulonglong2* __restrict__ pp =
                    (const ulonglong2*)(smem + OFF_P + s * PSLOT);   // 4 per step
                float4* __restrict__ wp =
                    (float4*)(smem + OFF_W + s * WSLOT);             // 2 per ckpt
                // distance-2 prefetch (tail overrun reads adjacent smem,
                // values rotated but never consumed)
                ulonglong2 a0 = pp[0], a1 = pp[1], a2 = pp[2], a3 = pp[3];
                ulonglong2 b0 = pp[4], b1 = pp[5], b2 = pp[6], b3 = pp[7];
                #pragma unroll 16
                for (int k = 0; k < KSTEPS; k++) {
                    if ((k & 3) == 0) {     // checkpoint: pre-step w_{c*K+k}
                        wp[(k >> 2) * 2 + 0] =
                            make_float4(flo(E0), fhi(E0), flo(O0), fhi(O0));
                        wp[(k >> 2) * 2 + 1] =
                            make_float4(flo(E1), fhi(E1), flo(O1), fhi(O1));
                    }
                    ulonglong2 c0 = pp[4 * k +  8];
                    // a_.x = even pair (p_e0,p_e1), a_.y = odd pair (helper layout)
                    ull mEa = add2(E0, a0.x);   // (m0,  m2)
                    ull mOa = add2(O0, a0.y);   // (m1,  m3)
                    ulonglong2 c1 = pp[4 * k +  9];
                    ull mEb = add2(E1, a1.x);   // (m4,  m6)
                    ull mOb = add2(O1, a1.y);   // (m5,  m7)
                    ulonglong2 c2 = pp[4 * k + 10];
                    ull mEc = add2(E0, a2.x);   // (m8,  m10)
                    ull mOc = add2(O0, a2.y);   // (m9,  m11)
                    ulonglong2 c3 = pp[4 * k + 11];
                    ull mEd = add2(E1, a3.x);   // (m12, m14)
                    ull mOd = add2(O1, a3.y);   // (m13, m15)
                    // o[q] = min(m[2q], m[2q+1]) -- scalar mins on components
                    float o0 = fminf(flo(mEa), flo(mOa));
                    float o1 = fminf(fhi(mEa), fhi(mOa));
                    float o2 = fminf(flo(mEb), flo(mOb));
                    float o3 = fminf(fhi(mEb), fhi(mOb));
                    float o4 = fminf(flo(mEc), flo(mOc));
                    float o5 = fminf(fhi(mEc), fhi(mOc));
                    float o6 = fminf(flo(mEd), flo(mOd));
                    float o7 = fminf(fhi(mEd), fhi(mOd));
                    E0 = fpack2(o0, o2); O0 = fpack2(o1, o3);
                    E1 = fpack2(o4, o6); O1 = fpack2(o5, o7);
                    a0 = b0; a1 = b1; a2 = b2; a3 = b3;
                    b0 = c0; b1 = c1; b2 = c2; b3 = c3;
                }
                mbar_arrive(sb + OFF_PC + 8 * s);
                mbar_arrive(sb + OFF_WF + 8 * s);
            }
        }
    } else if (wid < 2) {
        // -------- branch-metric producers: p[t][u] = |y[t] - sp[u]|,
        // written in split-pair order (4q, 4q+2, 4q+1, 4q+3) --------
        int base = wid * 32 + lane;         // 0..63
        int quad = base & 3;                // fixed 4-state group per lane
        float s0 = sp[quad * 4 + 0], s1 = sp[quad * 4 + 2];
        float s2 = sp[quad * 4 + 1], s3 = sp[quad * 4 + 3];
        for (int c = 0; c < NCHUNK; c++) {
            int s = c & 1;
            if (c >= NSLOTS) mbar_wait(sb + OFF_PC + 8 * s, ((c - NSLOTS) >> 1) & 1);
            float4* __restrict__ pb = (float4*)(smem + OFF_P + s * PSLOT);
            const float* yc = y + c * KSTEPS;
            #pragma unroll 4
            for (int it = 0; it < 64; it++) {
                int idx = it * 64 + base;
                int k = idx >> 2;           // step within chunk
                float yv = __ldg(&yc[k]);
                pb[k * 4 + quad] = make_float4(fabsf(yv - s0), fabsf(yv - s1),
                                               fabsf(yv - s2), fabsf(yv - s3));
            }
            mbar_arrive(sb + OFF_PF + 8 * s);
        }
    } else {
        // -------- bit extractors: out[n] = argmin(w_n) % 2. --------
        // Thread btid owns n = c*1024 + 4*btid + j (j=0..3): loads the
        // checkpoint w_{4J}, then replays up to 3 ACS steps from the p ring
        // (same ops, same order -> bit-exact) emitting a bit each time.
        // p visibility: helpers' PF release -> producer acquire -> producer's
        // WF release -> our acquire (release/acquire cumulativity).
        int b8 = (wid < 3) ? (wid - 2) : (wid < 7) ? (wid - 3)
                 : (wid < 11) ? (wid - 4) : (wid - 5);
        int btid = b8 * 32 + lane;          // 0..255
        for (int c = 0; c < NCHUNK; c++) {
            int s = c & 1;
            mbar_wait(sb + OFF_WF + 8 * s, (c >> 1) & 1);
            // checkpoint w_{c*1024 + 4*btid}, split-pair order
            const float4* wk = (const float4*)(smem + OFF_W + s * WSLOT) + btid * 2;
            float4 A = wk[0], B = wk[1];
            float w0 = A.x, w1 = A.z, w2 = A.y, w3 = A.w;
            float w4 = B.x, w5 = B.z, w6 = B.y, w7 = B.w;
            const float4* pk = (const float4*)(smem + OFF_P + s * PSLOT) + (4 * btid) * 4;
            float bits[4];
            #pragma unroll
            for (int j = 0; j < 4; j++) {
                bits[j] = bit_of(w0, w1, w2, w3, w4, w5, w6, w7);
                if (j < 3) {
                    // ACS with p at step k = 4*btid + j (split-pair quads)
                    float4 q0 = pk[j * 4 + 0], q1 = pk[j * 4 + 1];
                    float4 q2 = pk[j * 4 + 2], q3 = pk[j * 4 + 3];
                    float p0 = q0.x, p1 = q0.z, p2  = q0.y, p3  = q0.w;
                    float p4 = q1.x, p5 = q1.z, p6  = q1.y, p7  = q1.w;
                    float p8 = q2.x, p9 = q2.z, p10 = q2.y, p11 = q2.w;
                    float p12 = q3.x, p13 = q3.z, p14 = q3.y, p15 = q3.w;
                    float n0 = fminf(w0 + p0,  w1 + p1);
                    float n1 = fminf(w2 + p2,  w3 + p3);
                    float n2 = fminf(w4 + p4,  w5 + p5);
                    float n3 = fminf(w6 + p6,  w7 + p7);
                    float n4 = fminf(w0 + p8,  w1 + p9);
                    float n5 = fminf(w2 + p10, w3 + p11);
                    float n6 = fminf(w4 + p12, w5 + p13);
                    float n7 = fminf(w6 + p14, w7 + p15);
                    w0 = n0; w1 = n1; w2 = n2; w3 = n3;
                    w4 = n4; w5 = n5; w6 = n6; w7 = n7;
                }
            }
            *(float4*)(out + (size_t)c * KSTEPS + 4 * btid) =
                make_float4(bits[0], bits[1], bits[2], bits[3]);
            __syncwarp();
            if (lane == 0) {
                mbar_arrive(sb + OFF_WE + 8 * s);
                mbar_arrive(sb + OFF_PC + 8 * s);
            }
        }
    }
}

extern "C" void kernel_launch(void* const* d_in, const int* in_sizes, int n_in,
                              void* d_out, int out_size)
{
    const float* a = (const float*)d_in[0];
    const float* b = (const float*)d_in[1];
    const float* y;
    const float* sp;
    if (in_sizes[0] == 16) { sp = a; y = b; }
    else                   { y = a;  sp = b; }

    cudaFuncSetAttribute(va_main, cudaFuncAttributeMaxDynamicSharedMemorySize, SMEM_SZ);
    va_main<<<1, 448, SMEM_SZ>>>(y, sp, (float*)d_out);
}

// round 16
// speedup vs baseline: 1.2580x; 1.0031x over previous
#include <cuda_runtime.h>
#include <cstdint>

#define T_LEN   1048576
#define KSTEPS  1024
#define NSLOTS  2
#define NCHUNK  (T_LEN / KSTEPS)

// shared memory layout (bytes)
#define OFF_PF   0                         // p_full[2]   (8B each)
#define OFF_PC   32                        // p_cons[2]
#define OFF_WF   64                        // w_full[2]
#define OFF_WE   96                        // w_free[2]
#define OFF_P    256                       // p ring: 2 slots x 1024 steps x 64B
#define PSLOT    (KSTEPS * 64)
#define OFF_W    (OFF_P + NSLOTS * PSLOT)  // w ring: 2 slots x 128 ckpts x 32B
#define WSLOT    (KSTEPS / 8 * 32)
#define SMEM_SZ  (OFF_W + NSLOTS * WSLOT + 256)  // pad for prefetch overrun

typedef unsigned long long ull;
typedef unsigned int u32;

__device__ __forceinline__ void mbar_init(u32 a, u32 cnt) {
    asm volatile("mbarrier.init.shared.b64 [%0], %1;" :: "r"(a), "r"(cnt) : "memory");
}
__device__ __forceinline__ void mbar_arrive(u32 a) {
    asm volatile("mbarrier.arrive.release.cta.shared::cta.b64 _, [%0];" :: "r"(a) : "memory");
}
__device__ __forceinline__ void mbar_wait(u32 a, u32 par) {
    u32 done;
    asm volatile(
        "{\n\t.reg .pred p;\n\t"
        "mbarrier.try_wait.parity.acquire.cta.shared::cta.b64 p, [%1], %2;\n\t"
        "selp.b32 %0, 1, 0, p;\n\t}"
        : "=r"(done) : "r"(a), "r"(par) : "memory");
    if (!done) {
        asm volatile(
            "{\n\t.reg .pred P1;\n\t"
            "WL_%=:\n\t"
            "mbarrier.try_wait.parity.acquire.cta.shared::cta.b64 P1, [%0], %1, 0x989680;\n\t"
            "@P1 bra.uni WD_%=;\n\t"
            "bra.uni WL_%=;\n\t"
            "WD_%=:\n\t}"
            :: "r"(a), "r"(par) : "memory");
    }
}

// packed add: two bit-exact IEEE-rn f32 adds in one instruction.
__device__ __forceinline__ ull add2(ull a, ull c) {
    ull r; asm("add.rn.f32x2 %0, %1, %2;" : "=l"(r) : "l"(a), "l"(c));
    return r;
}
// pack/unpack in C++: resolved by register allocation, not real MOVs.
__device__ __forceinline__ ull fpack2(float lo, float hi) {
    union { float f[2]; ull u; } v; v.f[0] = lo; v.f[1] = hi; return v.u;
}
__device__ __forceinline__ float flo(ull x) {
    union { ull u; float f[2]; } v; v.u = x; return v.f[0];
}
__device__ __forceinline__ float fhi(ull x) {
    union { ull u; float f[2]; } v; v.u = x; return v.f[1];
}

// first-index argmin over logical w0..w7, return (idx & 1) as float.
// strict < keeps lowest index = jnp.argmin tie-break on the duplicated 16-vec.
__device__ __forceinline__ float bit_of(float w0, float w1, float w2, float w3,
                                        float w4, float w5, float w6, float w7) {
    float best = w0; int bi = 0;
    if (w1 < best) { best = w1; bi = 1; }
    if (w2 < best) { best = w2; bi = 2; }
    if (w3 < best) { best = w3; bi = 3; }
    if (w4 < best) { best = w4; bi = 4; }
    if (w5 < best) { best = w5; bi = 5; }
    if (w6 < best) { best = w6; bi = 6; }
    if (w7 < best) {            bi = 7; }
    return (float)(bi & 1);
}

__global__ void __launch_bounds__(448, 1)
va_main(const float* __restrict__ y, const float* __restrict__ sp, float* __restrict__ out)
{
    extern __shared__ char smem[];
    u32 sb = (u32)__cvta_generic_to_shared(smem);
    int tid = threadIdx.x, wid = tid >> 5, lane = tid & 31;

    if (tid == 0) {
        for (int s = 0; s < NSLOTS; s++) {
            mbar_init(sb + OFF_PF + 8 * s, 64); // 64 fetch lanes arrive
            mbar_init(sb + OFF_PC + 8 * s, 9);  // producer + 8 bit leaders
            mbar_init(sb + OFF_WF + 8 * s, 1);  // producer arrives
            mbar_init(sb + OFF_WE + 8 * s, 8);  // 8 bit-warp leaders arrive
        }
    }
    __syncthreads();

    // wid%4 = SMSP. Producer = wid 11, alone on SMSP3 (3, 7, 13 exit).
    if (wid == 3 || wid == 7 || wid == 13) return;

    if (wid == 11) {
        // -------- serial Viterbi producer, private SMSP --------
        // Split-pair layout: E0=(w0,w2) O0=(w1,w3) E1=(w4,w6) O1=(w5,w7).
        // 8 packed ADD2 + 8 scalar FMNMX per step; distance-2 prefetch.
        // Checkpoints every 8 steps (pre-step w at k%8==0); bit warps replay
        // the <=7 intermediate ACS steps themselves (bit-exact).
        if (lane == 0) {
            ull E0 = 0ull, O0 = 0ull, E1 = 0ull, O1 = 0ull;
            for (int c = 0; c < NCHUNK; c++) {
                int s = c & 1;
                mbar_wait(sb + OFF_PF + 8 * s, (c >> 1) & 1);
                if (c >= NSLOTS) mbar_wait(sb + OFF_WE + 8 * s, ((c - NSLOTS) >> 1) & 1);
                const ulonglong2* __restrict__ pp =
                    (const ulonglong2*)(smem + OFF_P + s * PSLOT);   // 4 per step
                float4* __restrict__ wp =
                    (float4*)(smem + OFF_W + s * WSLOT);             // 2 per ckpt
                // distance-2 prefetch (tail overrun reads adjacent smem,
                // values rotated but never consumed)
                ulonglong2 a0 = pp[0], a1 = pp[1], a2 = pp[2], a3 = pp[3];
                ulonglong2 b0 = pp[4], b1 = pp[5], b2 = pp[6], b3 = pp[7];
                #pragma unroll 16
                for (int k = 0; k < KSTEPS; k++) {
                    if ((k & 7) == 0) {     // checkpoint: pre-step w_{c*K+k}
                        wp[(k >> 3) * 2 + 0] =
                            make_float4(flo(E0), fhi(E0), flo(O0), fhi(O0));
                        wp[(k >> 3) * 2 + 1] =
                            make_float4(flo(E1), fhi(E1), flo(O1), fhi(O1));
                    }
                    ulonglong2 c0 = pp[4 * k +  8];
                    // a_.x = even pair (p_e0,p_e1), a_.y = odd pair (helper layout)
                    ull mEa = add2(E0, a0.x);   // (m0,  m2)
                    ull mOa = add2(O0, a0.y);   // (m1,  m3)
                    ulonglong2 c1 = pp[4 * k +  9];
                    ull mEb = add2(E1, a1.x);   // (m4,  m6)
                    ull mOb = add2(O1, a1.y);   // (m5,  m7)
                    ulonglong2 c2 = pp[4 * k + 10];
                    ull mEc = add2(E0, a2.x);   // (m8,  m10)
                    ull mOc = add2(O0, a2.y);   // (m9,  m11)
                    ulonglong2 c3 = pp[4 * k + 11];
                    ull mEd = add2(E1, a3.x);   // (m12, m14)
                    ull mOd = add2(O1, a3.y);   // (m13, m15)
                    // o[q] = min(m[2q], m[2q+1]) -- scalar mins on components
                    float o0 = fminf(flo(mEa), flo(mOa));
                    float o1 = fminf(fhi(mEa), fhi(mOa));
                    float o2 = fminf(flo(mEb), flo(mOb));
                    float o3 = fminf(fhi(mEb), fhi(mOb));
                    float o4 = fminf(flo(mEc), flo(mOc));
                    float o5 = fminf(fhi(mEc), fhi(mOc));
                    float o6 = fminf(flo(mEd), flo(mOd));
                    float o7 = fminf(fhi(mEd), fhi(mOd));
                    E0 = fpack2(o0, o2); O0 = fpack2(o1, o3);
                    E1 = fpack2(o4, o6); O1 = fpack2(o5, o7);
                    a0 = b0; a1 = b1; a2 = b2; a3 = b3;
                    b0 = c0; b1 = c1; b2 = c2; b3 = c3;
                }
                mbar_arrive(sb + OFF_PC + 8 * s);
                mbar_arrive(sb + OFF_WF + 8 * s);
            }
        }
    } else if (wid < 2) {
        // -------- branch-metric producers: p[t][u] = |y[t] - sp[u]|,
        // written in split-pair order (4q, 4q+2, 4q+1, 4q+3) --------
        int base = wid * 32 + lane;         // 0..63
        int quad = base & 3;                // fixed 4-state group per lane
        float s0 = sp[quad * 4 + 0], s1 = sp[quad * 4 + 2];
        float s2 = sp[quad * 4 + 1], s3 = sp[quad * 4 + 3];
        for (int c = 0; c < NCHUNK; c++) {
            int s = c & 1;
            if (c >= NSLOTS) mbar_wait(sb + OFF_PC + 8 * s, ((c - NSLOTS) >> 1) & 1);
            float4* __restrict__ pb = (float4*)(smem + OFF_P + s * PSLOT);
            const float* yc = y + c * KSTEPS;
            #pragma unroll 4
            for (int it = 0; it < 64; it++) {
                int idx = it * 64 + base;
                int k = idx >> 2;           // step within chunk
                float yv = __ldg(&yc[k]);
                pb[k * 4 + quad] = make_float4(fabsf(yv - s0), fabsf(yv - s1),
                                               fabsf(yv - s2), fabsf(yv - s3));
            }
            mbar_arrive(sb + OFF_PF + 8 * s);
        }
    } else {
        // -------- bit extractors: out[n] = argmin(w_n) % 2. --------
        // Thread btid owns n = c*1024 + 4*btid + j (j=0..3). Checkpoint at
        // step 8*(btid>>1); odd btid silently replays 4 steps first. Replay
        // reads p from the ring (same ops, same order -> bit-exact).
        int b8 = (wid < 3) ? (wid - 2) : (wid < 7) ? (wid - 3)
                 : (wid < 11) ? (wid - 4) : (wid - 5);
        int btid = b8 * 32 + lane;          // 0..255
        int g = btid >> 1;                  // checkpoint group
        int r0 = (btid & 1) * 4;            // silent replay steps
        for (int c = 0; c < NCHUNK; c++) {
            int s = c & 1;
            mbar_wait(sb + OFF_WF + 8 * s, (c >> 1) & 1);
            // checkpoint w at chunk step 8*g, split-pair order
            const float4* wk = (const float4*)(smem + OFF_W + s * WSLOT) + g * 2;
            float4 A = wk[0], B = wk[1];
            float w0 = A.x, w1 = A.z, w2 = A.y, w3 = A.w;
            float w4 = B.x, w5 = B.z, w6 = B.y, w7 = B.w;
            const float4* pk = (const float4*)(smem + OFF_P + s * PSLOT) + (8 * g) * 4;
            // silent replay (odd btid: 4 steps)
            for (int j = 0; j < r0; j++) {
                float4 q0 = pk[j * 4 + 0], q1 = pk[j * 4 + 1];
                float4 q2 = pk[j * 4 + 2], q3 = pk[j * 4 + 3];
                float n0 = fminf(w0 + q0.x, w1 + q0.z);
                float n1 = fminf(w2 + q0.y, w3 + q0.w);
                float n2 = fminf(w4 + q1.x, w5 + q1.z);
                float n3 = fminf(w6 + q1.y, w7 + q1.w);
                float n4 = fminf(w0 + q2.x, w1 + q2.z);
                float n5 = fminf(w2 + q2.y, w3 + q2.w);
                float n6 = fminf(w4 + q3.x, w5 + q3.z);
                float n7 = fminf(w6 + q3.y, w7 + q3.w);
                w0 = n0; w1 = n1; w2 = n2; w3 = n3;
                w4 = n4; w5 = n5; w6 = n6; w7 = n7;
            }
            float bits[4];
            #pragma unroll
            for (int j = 0; j < 4; j++) {
                bits[j] = bit_of(w0, w1, w2, w3, w4, w5, w6, w7);
                if (j < 3) {
                    int jj = r0 + j;
                    float4 q0 = pk[jj * 4 + 0], q1 = pk[jj * 4 + 1];
                    float4 q2 = pk[jj * 4 + 2], q3 = pk[jj * 4 + 3];
                    float n0 = fminf(w0 + q0.x, w1 + q0.z);
                    float n1 = fminf(w2 + q0.y, w3 + q0.w);
                    float n2 = fminf(w4 + q1.x, w5 + q1.z);
                    float n3 = fminf(w6 + q1.y, w7 + q1.w);
                    float n4 = fminf(w0 + q2.x, w1 + q2.z);
                    float n5 = fminf(w2 + q2.y, w3 + q2.w);
                    float n6 = fminf(w4 + q3.x, w5 + q3.z);
                    float n7 = fminf(w6 + q3.y, w7 + q3.w);
                    w0 = n0; w1 = n1; w2 = n2; w3 = n3;
                    w4 = n4; w5 = n5; w6 = n6; w7 = n7;
                }
            }
            *(float4*)(out + (size_t)c * KSTEPS + 4 * btid) =
                make_float4(bits[0], bits[1], bits[2], bits[3]);
            __syncwarp();
            if (lane == 0) {
                mbar_arrive(sb + OFF_WE + 8 * s);
                mbar_arrive(sb + OFF_PC + 8 * s);
            }
        }
    }
}

extern "C" void kernel_launch(void* const* d_in, const int* in_sizes, int n_in,
                              void* d_out, int out_size)
{
    const float* a = (const float*)d_in[0];
    const float* b = (const float*)d_in[1];
    const float* y;
    const float* sp;
    if (in_sizes[0] == 16) { sp = a; y = b; }
    else                   { y = a;  sp = b; }

    cudaFuncSetAttribute(va_main, cudaFuncAttributeMaxDynamicSharedMemorySize, SMEM_SZ);
    va_main<<<1, 448, SMEM_SZ>>>(y, sp, (float*)d_out);
}